// round 15
// baseline (speedup 1.0000x reference)
#include <cuda_runtime.h>
#include <cuda_bf16.h>
#include <math.h>

#define NIMG 8
#define CH 512
#define HH 50
#define WW 62
#define HW 3100            // 50*62
#define NANCH 27900        // HW*9
#define NPAD 32768
#define NPRE 6000
#define NPOST 300
#define NWORDS 188         // ceil(6000/32)

#define OFF_SCORES 892800
#define OFF_ROIS   1339200
#define OFF_RIDX   1348800
#define OFF_ANCH   1351200

// conv dynamic smem layout (bytes):
//   As2 (u64 dup weights)  [0, 36864)          4608 u64: [ci8][tap9][oc64]
//   BpS (float staging)    [36864, 45568)      8*4*68 floats, rows padded to 68
//   Bp3 (u64 pixel pairs)  [45568, 70144)      3072 u64: [dx3][ci8][r4][pair32]
#define CONV_SMEM 70144
#define AS2_OFF 0
#define BPS_OFF 36864
#define BP3_OFF 45568

// ---------------- scratch (device globals; no allocation) ----------------
__device__ float              g_hpart[(size_t)8 * NIMG * HW * CH];
__device__ float              g_h[NIMG * HW * CH];
__device__ float              g_wt[9 * CH * CH];
__device__ float              g_fg[NIMG * NANCH];
__device__ float              g_roi[NIMG * NANCH * 4];
__device__ float              g_anchor[NANCH * 4];
__device__ unsigned long long g_skey[NIMG * NPAD];
__device__ float              g_topbox[NIMG * NPRE * 4];
__device__ unsigned int       g_topkey[NIMG * NPRE];
__device__ int                g_sel[NIMG * NPOST];
__device__ int                g_val[NIMG * NPOST];

__device__ __forceinline__ unsigned int packf(float f) {
    unsigned int u = __float_as_uint(f);
    return (u & 0x80000000u) ? ~u : (u | 0x80000000u);
}
#define NEGINF_KEY 0x007FFFFFu

__device__ __forceinline__ float read_scalar(const void* p) {
    int iv = *(const int*)p;
    float fv = *(const float*)p;
    if (iv > 0 && iv < 100000) return (float)iv;
    return fv;
}

// ---------------- 0: weight transpose ----------------
__global__ void wtrans_kernel(const float* __restrict__ w) {
    int t = blockIdx.x * 256 + threadIdx.x;
    if (t >= CH * CH * 9) return;
    int tap = t % 9;
    int ci  = (t / 9) % CH;
    int oc  = t / (9 * CH);
    g_wt[(tap * CH + ci) * CH + oc] = w[t];
}

// ---------------- 1a: conv chunk kernel, FFMA2 (f32x2) ----------------
// One 64-ci chunk per block. Per-component FMA chain identical to the passing
// kernel (c0 asc within chunk, ci, tap); fma.rn.f32x2 lanes are independent
// correctly-rounded fp32 FMAs -> bit-exact.
// Weights duplicated into both lanes AT LOAD TIME (As2). Pixel pairs are
// natural adjacent floats, pre-packed per-dx (Bp3) so all hot-loop shared
// loads are aligned u64/v2.u64.
extern __shared__ unsigned char conv_sm[];
__global__ void __launch_bounds__(256) conv_chunk_kernel(const float* __restrict__ x)
{
    unsigned long long* As2 = (unsigned long long*)(conv_sm + AS2_OFF);
    float*              BpS = (float*)(conv_sm + BPS_OFF);
    unsigned long long* Bp3 = (unsigned long long*)(conv_sm + BP3_OFF);

    int tid = threadIdx.x;
    int ty = tid >> 4;
    int tx = tid & 15;
    int y0  = blockIdx.x;
    int ocB = blockIdx.y * 64;
    int z   = blockIdx.z;
    int n   = z >> 3;
    int v   = z & 7;

    // zero BpS pad columns 64..67 once (stay zero across cb iterations)
    if (tid < 128) {
        int ci = tid >> 4, r = (tid >> 2) & 3, c = 64 + (tid & 3);
        BpS[ci * 272 + r * 68 + c] = 0.f;
    }

    unsigned long long acc[4][2];
#pragma unroll
    for (int i = 0; i < 4; i++) { acc[i][0] = 0ull; acc[i][1] = 0ull; }

#pragma unroll 1
    for (int cb = 0; cb < 8; cb++) {
        int c0 = v * 64 + cb * 8;
        // weights -> dup-packed u64
#pragma unroll
        for (int l = 0; l < 18; l++) {
            int t2 = tid + l * 256;
            int oc  = t2 & 63;
            int rest = t2 >> 6;
            int tap = rest % 9;
            int ci  = rest / 9;
            unsigned int wb = __float_as_uint(
                g_wt[((size_t)tap * CH + c0 + ci) * CH + ocB + oc]);
            As2[ci * 576 + tap * 64 + oc] =
                (unsigned long long)wb * 0x100000001ULL;
        }
        // input patch -> scalar staging (row stride 68, cols 0..63)
#pragma unroll
        for (int l = 0; l < 8; l++) {
            int t2 = tid + l * 256;
            int c  = t2 & 63;
            int r  = (t2 >> 6) & 3;
            int ci = t2 >> 8;
            int yy = y0 + r - 1;
            int xx = c - 1;
            float vv = 0.f;
            if (yy >= 0 && yy < HH && xx >= 0 && xx < WW)
                vv = x[(((size_t)n * CH + c0 + ci) * HH + yy) * WW + xx];
            BpS[ci * 272 + r * 68 + c] = vv;
        }
        __syncthreads();

        // build per-dx pixel pairs: 3072 u64, 12 per thread
#pragma unroll
        for (int l = 0; l < 12; l++) {
            int id = tid + l * 256;
            int p  = id & 31;
            int r  = (id >> 5) & 3;
            int ci = (id >> 7) & 7;
            int dx = id >> 10;
            int f0 = 4 * (p >> 1) + dx + 2 * (p & 1);
            const float* row = &BpS[ci * 272 + r * 68];
            unsigned long long pk =
                (unsigned long long)__float_as_uint(row[f0])
              | ((unsigned long long)__float_as_uint(row[f0 + 1]) << 32);
            Bp3[id] = pk;
        }
        __syncthreads();

#pragma unroll
        for (int ci = 0; ci < 8; ci++) {
#pragma unroll
            for (int tap = 0; tap < 9; tap++) {
                const int dy = tap / 3, dx = tap % 3;
                const unsigned long long* ap = &As2[ci * 576 + tap * 64 + ty * 4];
                unsigned long long a0 = ap[0], a1 = ap[1], a2 = ap[2], a3 = ap[3];
                const unsigned long long* bp =
                    &Bp3[(((dx * 8 + ci) * 4 + dy) << 5) + tx * 2];
                unsigned long long b0 = bp[0], b1 = bp[1];
                asm("fma.rn.f32x2 %0, %1, %2, %0;" : "+l"(acc[0][0]) : "l"(a0), "l"(b0));
                asm("fma.rn.f32x2 %0, %1, %2, %0;" : "+l"(acc[0][1]) : "l"(a0), "l"(b1));
                asm("fma.rn.f32x2 %0, %1, %2, %0;" : "+l"(acc[1][0]) : "l"(a1), "l"(b0));
                asm("fma.rn.f32x2 %0, %1, %2, %0;" : "+l"(acc[1][1]) : "l"(a1), "l"(b1));
                asm("fma.rn.f32x2 %0, %1, %2, %0;" : "+l"(acc[2][0]) : "l"(a2), "l"(b0));
                asm("fma.rn.f32x2 %0, %1, %2, %0;" : "+l"(acc[2][1]) : "l"(a2), "l"(b1));
                asm("fma.rn.f32x2 %0, %1, %2, %0;" : "+l"(acc[3][0]) : "l"(a3), "l"(b0));
                asm("fma.rn.f32x2 %0, %1, %2, %0;" : "+l"(acc[3][1]) : "l"(a3), "l"(b1));
            }
        }
        __syncthreads();
    }

    size_t vbase = (size_t)v * NIMG * HW * CH;
#pragma unroll
    for (int i = 0; i < 4; i++) {
        int oc = ocB + ty * 4 + i;
#pragma unroll
        for (int q = 0; q < 2; q++) {
            unsigned long long a = acc[i][q];
            float lo = __uint_as_float((unsigned int)(a & 0xFFFFFFFFull));
            float hi = __uint_as_float((unsigned int)(a >> 32));
            int p0 = tx * 4 + 2 * q;
            int p1 = p0 + 1;
            if (p0 < WW)
                g_hpart[vbase + ((size_t)n * HW + y0 * WW + p0) * CH + oc] = lo;
            if (p1 < WW)
                g_hpart[vbase + ((size_t)n * HW + y0 * WW + p1) * CH + oc] = hi;
        }
    }
}

// ---------------- 1b: combine partials (exact pairwise tree) + bias + ReLU ----------------
__global__ void conv_combine_kernel(const float* __restrict__ bias) {
    int t = blockIdx.x * 256 + threadIdx.x;
    const int TOT = NIMG * HW * CH;
    if (t >= TOT) return;
    int oc = t & (CH - 1);
    const size_t S = (size_t)NIMG * HW * CH;
    float a0 = g_hpart[t];
    float a1 = g_hpart[S + t];
    float a2 = g_hpart[2 * S + t];
    float a3 = g_hpart[3 * S + t];
    float a4 = g_hpart[4 * S + t];
    float a5 = g_hpart[5 * S + t];
    float a6 = g_hpart[6 * S + t];
    float a7 = g_hpart[7 * S + t];
    float s01 = __fadd_rn(a0, a1);
    float s23 = __fadd_rn(a2, a3);
    float s45 = __fadd_rn(a4, a5);
    float s67 = __fadd_rn(a6, a7);
    float r = __fadd_rn(__fadd_rn(s01, s23), __fadd_rn(s45, s67));
    float vv = r + bias[oc];
    g_h[t] = fmaxf(vv, 0.f);
}

// ---------------- 2: head 1x1 convs ----------------
__global__ void heads_kernel(const float* __restrict__ loc_w, const float* __restrict__ loc_b,
                             const float* __restrict__ sc_w,  const float* __restrict__ sc_b,
                             float* __restrict__ out)
{
    __shared__ float hs[8 * CH];
    int g = blockIdx.x;
    int n = g / 388;
    int p0 = (g % 388) * 8;
    for (int l = threadIdx.x; l < 8 * CH; l += 256) {
        int pp = l >> 9, c = l & 511;
        int p = p0 + pp;
        hs[l] = (p < HW) ? g_h[((size_t)n * HW + p) * CH + c] : 0.f;
    }
    __syncthreads();
    for (int job = threadIdx.x; job < 432; job += 256) {
        int pp = job / 54, o = job % 54;
        int p = p0 + pp;
        if (p >= HW) continue;
        const float* wrow;
        float b;
        if (o < 36) { wrow = loc_w + o * CH; b = loc_b[o]; }
        else        { wrow = sc_w + (o - 36) * CH; b = sc_b[o - 36]; }
        const float* h = &hs[pp * CH];
        float sv[8];
#pragma unroll
        for (int v = 0; v < 8; v++) {
            float s = 0.f;
            int base = v * 64;
#pragma unroll 8
            for (int c = 0; c < 64; c++)
                s = fmaf(h[base + c], wrow[base + c], s);
            sv[v] = s;
        }
        float s01 = __fadd_rn(sv[0], sv[1]);
        float s23 = __fadd_rn(sv[2], sv[3]);
        float s45 = __fadd_rn(sv[4], sv[5]);
        float s67 = __fadd_rn(sv[6], sv[7]);
        float s = __fadd_rn(__fadd_rn(s01, s23), __fadd_rn(s45, s67)) + b;
        if (o < 36) out[(size_t)n * 111600 + p * 36 + o] = s;
        else        out[OFF_SCORES + (size_t)n * 55800 + p * 18 + (o - 36)] = s;
    }
}

// ---------------- 2b: softmax fg scores ----------------
__global__ void fg_kernel(const float* __restrict__ out) {
    int t = blockIdx.x * 256 + threadIdx.x;
    if (t >= NIMG * NANCH) return;
    int n = t / NANCH, i = t % NANCH;
    int p = i / 9, a = i % 9;
    const float* s = out + OFF_SCORES + (size_t)n * 55800 + p * 18 + a * 2;
    float s0 = s[0], s1 = s[1];
    float m = fmaxf(s0, s1);
    float e0 = expf(s0 - m);
    float e1 = expf(s1 - m);
    g_fg[t] = e1 / (e0 + e1);
}

// ---------------- 3: anchors ----------------
__global__ void anchor_kernel(float* __restrict__ out) {
    int t = blockIdx.x * 256 + threadIdx.x;
    if (t >= NANCH) return;
    int p = t / 9, a = t % 9;
    int y = p / WW, x = p - y * WW;
    int ridx = a / 3, sidx = a % 3;
    double r = (ridx == 0) ? 0.5 : ((ridx == 1) ? 1.0 : 2.0);
    double s = (sidx == 0) ? 8.0 : ((sidx == 1) ? 16.0 : 32.0);
    double hb = 16.0 * s * sqrt(r);
    double wb = 16.0 * s * sqrt(1.0 / r);
    float a0 = (float)(8.0 - hb / 2.0);
    float a1 = (float)(8.0 - wb / 2.0);
    float a2 = (float)(8.0 + hb / 2.0);
    float a3 = (float)(8.0 + wb / 2.0);
    float sy = (float)y * 16.0f, sx = (float)x * 16.0f;
    float v0 = a0 + sy, v1 = a1 + sx;
    float v2 = a2 + sy, v3 = a3 + sx;
    g_anchor[t * 4 + 0] = v0; g_anchor[t * 4 + 1] = v1;
    g_anchor[t * 4 + 2] = v2; g_anchor[t * 4 + 3] = v3;
    out[OFF_ANCH + t * 4 + 0] = v0; out[OFF_ANCH + t * 4 + 1] = v1;
    out[OFF_ANCH + t * 4 + 2] = v2; out[OFF_ANCH + t * 4 + 3] = v3;
}

// ---------------- 4: decode boxes + clip + filter + pack sort keys ----------------
__global__ void decode_kernel(const float* __restrict__ out, const void* ph, const void* pw) {
    int t = blockIdx.x * 256 + threadIdx.x;
    if (t >= NIMG * NPAD) return;
    int n = t >> 15, i = t & (NPAD - 1);
    if (i >= NANCH) {
        g_skey[t] = (unsigned long long)(unsigned)(NPAD - 1 - i);
        return;
    }
    float fh = read_scalar(ph), fw = read_scalar(pw);
    const float* A = &g_anchor[i * 4];
    float ah = A[2] - A[0];
    float aw = A[3] - A[1];
    float cy = A[0] + 0.5f * ah;
    float cx = A[1] + 0.5f * aw;
    const float* L = out + (size_t)n * 111600 + (size_t)i * 4;
    float dy = L[0], dx = L[1], dh = L[2], dw = L[3];
    float ncy = dy * ah + cy;
    float ncx = dx * aw + cx;
    float nh = expf(dh) * ah;
    float nw = expf(dw) * aw;
    float b0 = ncy - 0.5f * nh;
    float b1 = ncx - 0.5f * nw;
    float b2 = ncy + 0.5f * nh;
    float b3 = ncx + 0.5f * nw;
    b0 = fminf(fmaxf(b0, 0.f), fh);
    b1 = fminf(fmaxf(b1, 0.f), fw);
    b2 = fminf(fmaxf(b2, 0.f), fh);
    b3 = fminf(fmaxf(b3, 0.f), fw);
    float hs = b2 - b0;
    float ws = b3 - b1;
    bool keep = (hs >= 16.f) && (ws >= 16.f);
    float sc = keep ? g_fg[n * NANCH + i] : -__int_as_float(0x7F800000);
    ((float4*)g_roi)[n * NANCH + i] = make_float4(b0, b1, b2, b3);
    g_skey[t] = ((unsigned long long)packf(sc) << 16)
              | (unsigned long long)(unsigned)(NPAD - 1 - i);
}

// ---------------- 5: tiled multi-kernel bitonic sort (desc u64) ----------------
#define TILE 2048

__global__ void __launch_bounds__(1024) sort_local_full() {
    __shared__ unsigned long long sk[TILE];
    int n = blockIdx.x >> 4;
    int T = blockIdx.x & 15;
    int tid = threadIdx.x;
    unsigned long long* base = g_skey + (size_t)n * NPAD + (size_t)T * TILE;
    sk[tid] = base[tid];
    sk[tid + 1024] = base[tid + 1024];
    __syncthreads();
    int gbase = T * TILE;
    for (int k = 2; k <= TILE; k <<= 1) {
        for (int j = k >> 1; j > 0; j >>= 1) {
            int i = ((tid & ~(j - 1)) << 1) | (tid & (j - 1));
            int ixj = i | j;
            int gi = gbase + i;
            unsigned long long a = sk[i], b = sk[ixj];
            bool doswap = (a < b) ^ ((gi & k) != 0);
            if (doswap) { sk[i] = b; sk[ixj] = a; }
            __syncthreads();
        }
    }
    base[tid] = sk[tid];
    base[tid + 1024] = sk[tid + 1024];
}

__global__ void sort_global_pass(int k, int j) {
    int t = blockIdx.x * 256 + threadIdx.x;
    if (t >= NIMG * NPAD / 2) return;
    int n = t / (NPAD / 2);
    int q = t % (NPAD / 2);
    int i = ((q & ~(j - 1)) << 1) | (q & (j - 1));
    int ixj = i | j;
    unsigned long long* base = g_skey + (size_t)n * NPAD;
    unsigned long long a = base[i], b = base[ixj];
    bool doswap = (a < b) ^ ((i & k) != 0);
    if (doswap) { base[i] = b; base[ixj] = a; }
}

__global__ void __launch_bounds__(1024) sort_local_tail(int k) {
    __shared__ unsigned long long sk[TILE];
    int n = blockIdx.x >> 4;
    int T = blockIdx.x & 15;
    int tid = threadIdx.x;
    unsigned long long* base = g_skey + (size_t)n * NPAD + (size_t)T * TILE;
    sk[tid] = base[tid];
    sk[tid + 1024] = base[tid + 1024];
    __syncthreads();
    int gbase = T * TILE;
    for (int j = 1024; j > 0; j >>= 1) {
        int i = ((tid & ~(j - 1)) << 1) | (tid & (j - 1));
        int ixj = i | j;
        int gi = gbase + i;
        unsigned long long a = sk[i], b = sk[ixj];
        bool doswap = (a < b) ^ ((gi & k) != 0);
        if (doswap) { sk[i] = b; sk[ixj] = a; }
        __syncthreads();
    }
    base[tid] = sk[tid];
    base[tid + 1024] = sk[tid + 1024];
}

__global__ void gather_kernel() {
    int t = blockIdx.x * 256 + threadIdx.x;
    if (t >= NIMG * NPRE) return;
    int n = t / NPRE, l = t % NPRE;
    unsigned long long pk = g_skey[(size_t)n * NPAD + l];
    unsigned int key = (unsigned int)(pk >> 16);
    int idx = NPAD - 1 - (int)(pk & 0xFFFFull);
    g_topkey[t] = key;
    ((float4*)g_topbox)[t] = ((const float4*)g_roi)[n * NANCH + idx];
}

// ---------------- 6: NMS, first-alive scan ----------------
#define NMS_CHUNK 6
__global__ void __launch_bounds__(1024) nms_kernel() {
    __shared__ unsigned int alive[NWORDS];
    __shared__ int s_first;
    int n = blockIdx.x;
    int tid = threadIdx.x;

    float4 myb[NMS_CHUNK];
#pragma unroll
    for (int k = 0; k < NMS_CHUNK; k++) {
        int l = tid + k * 1024;
        myb[k] = (l < NPRE) ? ((const float4*)g_topbox)[n * NPRE + l]
                            : make_float4(0, 0, 0, 0);
    }
    if (tid < NWORDS) {
        unsigned int m = 0;
        for (int b = 0; b < 32; b++) {
            int j = tid * 32 + b;
            if (j < NPRE && g_topkey[n * NPRE + j] > NEGINF_KEY) m |= (1u << b);
        }
        alive[tid] = m;
    }
    __syncthreads();

    int hintw = 0;
    for (int it = 0; it < NPOST; ++it) {
        if (tid == 0) {
            int w = hintw;
            while (w < NWORDS && alive[w] == 0u) w++;
            hintw = w;
            if (w < NWORDS) {
                int f = w * 32 + __ffs(alive[w]) - 1;
                s_first = f;
                g_sel[n * NPOST + it] = f;
                g_val[n * NPOST + it] = 1;
            } else {
                s_first = -1;
                g_sel[n * NPOST + it] = 0;
                g_val[n * NPOST + it] = 0;
            }
        }
        __syncthreads();
        int first = s_first;
        if (first >= 0) {
            float4 bj = ((const float4*)g_topbox)[n * NPRE + first];
            float aj = (bj.z - bj.x) * (bj.w - bj.y);
#pragma unroll
            for (int k = 0; k < NMS_CHUNK; k++) {
                int l = tid + k * 1024;
                if (l < NPRE) {
                    float4 B = myb[k];
                    float ty = fmaxf(bj.x, B.x), tx = fmaxf(bj.y, B.y);
                    float by = fminf(bj.z, B.z), bx = fminf(bj.w, B.w);
                    float ih = fmaxf(by - ty, 0.f);
                    float iw = fmaxf(bx - tx, 0.f);
                    float inter = __fmul_rn(ih, iw);
                    float hl = B.z - B.x;
                    float wl = B.w - B.y;
                    float den = (fmaf(hl, wl, aj) - inter) + 1e-10f;
                    float iou = inter / den;
                    if (iou > 0.7f)
                        atomicAnd(&alive[l >> 5], ~(1u << (l & 31)));
                }
            }
        }
        __syncthreads();
    }
}

// ---------------- 7: emit rois + roi_indices ----------------
__global__ void output_kernel(float* __restrict__ out) {
    int t = blockIdx.x * 256 + threadIdx.x;
    if (t >= NIMG * NPOST) return;
    int n = t / NPOST;
    int sel = g_sel[t];
    int val = g_val[t];
    float4 b = val ? ((const float4*)g_topbox)[n * NPRE + sel] : make_float4(0, 0, 0, 0);
    ((float4*)(out + OFF_ROIS))[t] = b;
    out[OFF_RIDX + t] = (float)n;
}

// ---------------- launch ----------------
extern "C" void kernel_launch(void* const* d_in, const int* in_sizes, int n_in,
                              void* d_out, int out_size)
{
    const float* x   = (const float*)d_in[0];
    const float* c1w = (const float*)d_in[1];
    const float* c1b = (const float*)d_in[2];
    const float* sw  = (const float*)d_in[3];
    const float* sb  = (const float*)d_in[4];
    const float* lw  = (const float*)d_in[5];
    const float* lb  = (const float*)d_in[6];
    const void*  ph  = d_in[7];
    const void*  pw  = d_in[8];
    float* out = (float*)d_out;

    wtrans_kernel<<<(CH * CH * 9 + 255) / 256, 256>>>(c1w);

    cudaFuncSetAttribute(conv_chunk_kernel,
                         cudaFuncAttributeMaxDynamicSharedMemorySize, CONV_SMEM);
    conv_chunk_kernel<<<dim3(HH, 8, NIMG * 8), 256, CONV_SMEM>>>(x);
    conv_combine_kernel<<<(NIMG * HW * CH + 255) / 256, 256>>>(c1b);

    heads_kernel<<<NIMG * 388, 256>>>(lw, lb, sw, sb, out);
    fg_kernel<<<(NIMG * NANCH + 255) / 256, 256>>>(out);
    anchor_kernel<<<(NANCH + 255) / 256, 256>>>(out);
    decode_kernel<<<(NIMG * NPAD) / 256, 256>>>(out, ph, pw);

    sort_local_full<<<NIMG * 16, 1024>>>();
    int npairs_blocks = (NIMG * NPAD / 2 + 255) / 256;
    for (int k = 4096; k <= NPAD; k <<= 1) {
        for (int j = k >> 1; j >= TILE; j >>= 1)
            sort_global_pass<<<npairs_blocks, 256>>>(k, j);
        sort_local_tail<<<NIMG * 16, 1024>>>(k);
    }
    gather_kernel<<<(NIMG * NPRE + 255) / 256, 256>>>();

    nms_kernel<<<NIMG, 1024>>>();
    output_kernel<<<(NIMG * NPOST + 255) / 256, 256>>>(out);
}

// round 16
// speedup vs baseline: 1.1655x; 1.1655x over previous
#include <cuda_runtime.h>
#include <cuda_bf16.h>
#include <math.h>

#define NIMG 8
#define CH 512
#define HH 50
#define WW 62
#define HW 3100            // 50*62
#define NANCH 27900        // HW*9
#define NPAD 32768
#define NPRE 6000
#define NPOST 300
#define NWORDS 188         // ceil(6000/32)

#define OFF_SCORES 892800
#define OFF_ROIS   1339200
#define OFF_RIDX   1348800
#define OFF_ANCH   1351200

// ---------------- scratch (device globals; no allocation) ----------------
__device__ float              g_hpart[(size_t)8 * NIMG * HW * CH];
__device__ float              g_h[NIMG * HW * CH];
__device__ float              g_wt[9 * CH * CH];
__device__ float              g_fg[NIMG * NANCH];
__device__ float              g_roi[NIMG * NANCH * 4];
__device__ float              g_anchor[NANCH * 4];
__device__ unsigned long long g_skey[NIMG * NPAD];
__device__ float              g_topbox[NIMG * NPRE * 4];
__device__ unsigned int       g_topkey[NIMG * NPRE];
__device__ int                g_sel[NIMG * NPOST];
__device__ int                g_val[NIMG * NPOST];

__device__ __forceinline__ unsigned int packf(float f) {
    unsigned int u = __float_as_uint(f);
    return (u & 0x80000000u) ? ~u : (u | 0x80000000u);
}
#define NEGINF_KEY 0x007FFFFFu

__device__ __forceinline__ float read_scalar(const void* p) {
    int iv = *(const int*)p;
    float fv = *(const float*)p;
    if (iv > 0 && iv < 100000) return (float)iv;
    return fv;
}

// ---------------- 0: weight transpose ----------------
__global__ void wtrans_kernel(const float* __restrict__ w) {
    int t = blockIdx.x * 256 + threadIdx.x;
    if (t >= CH * CH * 9) return;
    int tap = t % 9;
    int ci  = (t / 9) % CH;
    int oc  = t / (9 * CH);
    g_wt[(tap * CH + ci) * CH + oc] = w[t];
}

// ---------------- 1a: conv chunk kernel (R14 math, dx-shifted pixel copies) --------
// One 64-ci chunk per block. FMA chain per output IDENTICAL to R14 (c0 asc
// within chunk, ci, tap; same 16 fmaf per step). Only the pixel smem layout
// changed: 3 per-dx shifted copies so the inner pixel load is one aligned
// LDS.128 instead of 4 unaligned LDS.32 (inner smem requests 5 -> 2).
__global__ void __launch_bounds__(256) conv_chunk_kernel(const float* __restrict__ x)
{
    __shared__ float As[8 * 9 * 64];          // [ci][tap][oc]      9 KB
    __shared__ float Bp4[3 * 8 * 4 * 64];     // [dx][ci][r][col]  24 KB

    int tid = threadIdx.x;
    int ty = tid >> 4;
    int tx = tid & 15;
    int y0  = blockIdx.x;
    int ocB = blockIdx.y * 64;
    int z   = blockIdx.z;
    int n   = z >> 3;
    int v   = z & 7;

    float acc[4][4];
#pragma unroll
    for (int i = 0; i < 4; i++)
#pragma unroll
        for (int j = 0; j < 4; j++) acc[i][j] = 0.f;

#pragma unroll 1
    for (int cb = 0; cb < 8; cb++) {
        int c0 = v * 64 + cb * 8;
        // weights
#pragma unroll
        for (int l = 0; l < 18; l++) {
            int t2 = tid + l * 256;
            int oc  = t2 & 63;
            int rest = t2 >> 6;
            int tap = rest % 9;
            int ci  = rest / 9;
            As[ci * 576 + tap * 64 + oc] =
                g_wt[((size_t)tap * CH + c0 + ci) * CH + ocB + oc];
        }
        // input patch -> 3 dx-shifted copies
#pragma unroll
        for (int l = 0; l < 8; l++) {
            int t2 = tid + l * 256;
            int c  = t2 & 63;          // patch col: global x = c-1
            int r  = (t2 >> 6) & 3;    // patch row: global y = y0 + r - 1
            int ci = t2 >> 8;
            int yy = y0 + r - 1;
            int xx = c - 1;
            float vv = 0.f;
            if (yy >= 0 && yy < HH && xx >= 0 && xx < WW)
                vv = x[(((size_t)n * CH + c0 + ci) * HH + yy) * WW + xx];
#pragma unroll
            for (int dx = 0; dx < 3; dx++) {
                int p = c - dx;
                if (p >= 0)
                    Bp4[(((dx * 8 + ci) << 2) + r) * 64 + p] = vv;
            }
        }
        __syncthreads();

#pragma unroll
        for (int ci = 0; ci < 8; ci++) {
#pragma unroll
            for (int tap = 0; tap < 9; tap++) {
                const int dy = tap / 3, dx = tap % 3;
                const float4 a4 = *(const float4*)&As[ci * 576 + tap * 64 + ty * 4];
                const float4 b4 = *(const float4*)
                    &Bp4[(((dx * 8 + ci) << 2) + dy) * 64 + tx * 4];
                float b0 = b4.x, b1 = b4.y, b2 = b4.z, b3 = b4.w;
                acc[0][0] = fmaf(a4.x, b0, acc[0][0]);
                acc[0][1] = fmaf(a4.x, b1, acc[0][1]);
                acc[0][2] = fmaf(a4.x, b2, acc[0][2]);
                acc[0][3] = fmaf(a4.x, b3, acc[0][3]);
                acc[1][0] = fmaf(a4.y, b0, acc[1][0]);
                acc[1][1] = fmaf(a4.y, b1, acc[1][1]);
                acc[1][2] = fmaf(a4.y, b2, acc[1][2]);
                acc[1][3] = fmaf(a4.y, b3, acc[1][3]);
                acc[2][0] = fmaf(a4.z, b0, acc[2][0]);
                acc[2][1] = fmaf(a4.z, b1, acc[2][1]);
                acc[2][2] = fmaf(a4.z, b2, acc[2][2]);
                acc[2][3] = fmaf(a4.z, b3, acc[2][3]);
                acc[3][0] = fmaf(a4.w, b0, acc[3][0]);
                acc[3][1] = fmaf(a4.w, b1, acc[3][1]);
                acc[3][2] = fmaf(a4.w, b2, acc[3][2]);
                acc[3][3] = fmaf(a4.w, b3, acc[3][3]);
            }
        }
        __syncthreads();
    }

    size_t vbase = (size_t)v * NIMG * HW * CH;
#pragma unroll
    for (int j = 0; j < 4; j++) {
        int px = tx * 4 + j;
        if (px >= WW) continue;
        int p = y0 * WW + px;
#pragma unroll
        for (int i = 0; i < 4; i++) {
            int oc = ocB + ty * 4 + i;
            g_hpart[vbase + ((size_t)n * HW + p) * CH + oc] = acc[i][j];
        }
    }
}

// ---------------- 1b: combine partials (exact pairwise tree) + bias + ReLU ----------------
__global__ void conv_combine_kernel(const float* __restrict__ bias) {
    int t = blockIdx.x * 256 + threadIdx.x;
    const int TOT = NIMG * HW * CH;
    if (t >= TOT) return;
    int oc = t & (CH - 1);
    const size_t S = (size_t)NIMG * HW * CH;
    float a0 = g_hpart[t];
    float a1 = g_hpart[S + t];
    float a2 = g_hpart[2 * S + t];
    float a3 = g_hpart[3 * S + t];
    float a4 = g_hpart[4 * S + t];
    float a5 = g_hpart[5 * S + t];
    float a6 = g_hpart[6 * S + t];
    float a7 = g_hpart[7 * S + t];
    float s01 = __fadd_rn(a0, a1);
    float s23 = __fadd_rn(a2, a3);
    float s45 = __fadd_rn(a4, a5);
    float s67 = __fadd_rn(a6, a7);
    float r = __fadd_rn(__fadd_rn(s01, s23), __fadd_rn(s45, s67));
    float vv = r + bias[oc];
    g_h[t] = fmaxf(vv, 0.f);
}

// ---------------- 2: head 1x1 convs ----------------
__global__ void heads_kernel(const float* __restrict__ loc_w, const float* __restrict__ loc_b,
                             const float* __restrict__ sc_w,  const float* __restrict__ sc_b,
                             float* __restrict__ out)
{
    __shared__ float hs[8 * CH];
    int g = blockIdx.x;
    int n = g / 388;
    int p0 = (g % 388) * 8;
    for (int l = threadIdx.x; l < 8 * CH; l += 256) {
        int pp = l >> 9, c = l & 511;
        int p = p0 + pp;
        hs[l] = (p < HW) ? g_h[((size_t)n * HW + p) * CH + c] : 0.f;
    }
    __syncthreads();
    for (int job = threadIdx.x; job < 432; job += 256) {
        int pp = job / 54, o = job % 54;
        int p = p0 + pp;
        if (p >= HW) continue;
        const float* wrow;
        float b;
        if (o < 36) { wrow = loc_w + o * CH; b = loc_b[o]; }
        else        { wrow = sc_w + (o - 36) * CH; b = sc_b[o - 36]; }
        const float* h = &hs[pp * CH];
        float sv[8];
#pragma unroll
        for (int v = 0; v < 8; v++) {
            float s = 0.f;
            int base = v * 64;
#pragma unroll 8
            for (int c = 0; c < 64; c++)
                s = fmaf(h[base + c], wrow[base + c], s);
            sv[v] = s;
        }
        float s01 = __fadd_rn(sv[0], sv[1]);
        float s23 = __fadd_rn(sv[2], sv[3]);
        float s45 = __fadd_rn(sv[4], sv[5]);
        float s67 = __fadd_rn(sv[6], sv[7]);
        float s = __fadd_rn(__fadd_rn(s01, s23), __fadd_rn(s45, s67)) + b;
        if (o < 36) out[(size_t)n * 111600 + p * 36 + o] = s;
        else        out[OFF_SCORES + (size_t)n * 55800 + p * 18 + (o - 36)] = s;
    }
}

// ---------------- 2b: softmax fg scores ----------------
__global__ void fg_kernel(const float* __restrict__ out) {
    int t = blockIdx.x * 256 + threadIdx.x;
    if (t >= NIMG * NANCH) return;
    int n = t / NANCH, i = t % NANCH;
    int p = i / 9, a = i % 9;
    const float* s = out + OFF_SCORES + (size_t)n * 55800 + p * 18 + a * 2;
    float s0 = s[0], s1 = s[1];
    float m = fmaxf(s0, s1);
    float e0 = expf(s0 - m);
    float e1 = expf(s1 - m);
    g_fg[t] = e1 / (e0 + e1);
}

// ---------------- 3: anchors ----------------
__global__ void anchor_kernel(float* __restrict__ out) {
    int t = blockIdx.x * 256 + threadIdx.x;
    if (t >= NANCH) return;
    int p = t / 9, a = t % 9;
    int y = p / WW, x = p - y * WW;
    int ridx = a / 3, sidx = a % 3;
    double r = (ridx == 0) ? 0.5 : ((ridx == 1) ? 1.0 : 2.0);
    double s = (sidx == 0) ? 8.0 : ((sidx == 1) ? 16.0 : 32.0);
    double hb = 16.0 * s * sqrt(r);
    double wb = 16.0 * s * sqrt(1.0 / r);
    float a0 = (float)(8.0 - hb / 2.0);
    float a1 = (float)(8.0 - wb / 2.0);
    float a2 = (float)(8.0 + hb / 2.0);
    float a3 = (float)(8.0 + wb / 2.0);
    float sy = (float)y * 16.0f, sx = (float)x * 16.0f;
    float v0 = a0 + sy, v1 = a1 + sx;
    float v2 = a2 + sy, v3 = a3 + sx;
    g_anchor[t * 4 + 0] = v0; g_anchor[t * 4 + 1] = v1;
    g_anchor[t * 4 + 2] = v2; g_anchor[t * 4 + 3] = v3;
    out[OFF_ANCH + t * 4 + 0] = v0; out[OFF_ANCH + t * 4 + 1] = v1;
    out[OFF_ANCH + t * 4 + 2] = v2; out[OFF_ANCH + t * 4 + 3] = v3;
}

// ---------------- 4: decode boxes + clip + filter + pack sort keys ----------------
__global__ void decode_kernel(const float* __restrict__ out, const void* ph, const void* pw) {
    int t = blockIdx.x * 256 + threadIdx.x;
    if (t >= NIMG * NPAD) return;
    int n = t >> 15, i = t & (NPAD - 1);
    if (i >= NANCH) {
        g_skey[t] = (unsigned long long)(unsigned)(NPAD - 1 - i);
        return;
    }
    float fh = read_scalar(ph), fw = read_scalar(pw);
    const float* A = &g_anchor[i * 4];
    float ah = A[2] - A[0];
    float aw = A[3] - A[1];
    float cy = A[0] + 0.5f * ah;
    float cx = A[1] + 0.5f * aw;
    const float* L = out + (size_t)n * 111600 + (size_t)i * 4;
    float dy = L[0], dx = L[1], dh = L[2], dw = L[3];
    float ncy = dy * ah + cy;
    float ncx = dx * aw + cx;
    float nh = expf(dh) * ah;
    float nw = expf(dw) * aw;
    float b0 = ncy - 0.5f * nh;
    float b1 = ncx - 0.5f * nw;
    float b2 = ncy + 0.5f * nh;
    float b3 = ncx + 0.5f * nw;
    b0 = fminf(fmaxf(b0, 0.f), fh);
    b1 = fminf(fmaxf(b1, 0.f), fw);
    b2 = fminf(fmaxf(b2, 0.f), fh);
    b3 = fminf(fmaxf(b3, 0.f), fw);
    float hs = b2 - b0;
    float ws = b3 - b1;
    bool keep = (hs >= 16.f) && (ws >= 16.f);
    float sc = keep ? g_fg[n * NANCH + i] : -__int_as_float(0x7F800000);
    ((float4*)g_roi)[n * NANCH + i] = make_float4(b0, b1, b2, b3);
    g_skey[t] = ((unsigned long long)packf(sc) << 16)
              | (unsigned long long)(unsigned)(NPAD - 1 - i);
}

// ---------------- 5: tiled multi-kernel bitonic sort (desc u64) ----------------
#define TILE 2048

__global__ void __launch_bounds__(1024) sort_local_full() {
    __shared__ unsigned long long sk[TILE];
    int n = blockIdx.x >> 4;
    int T = blockIdx.x & 15;
    int tid = threadIdx.x;
    unsigned long long* base = g_skey + (size_t)n * NPAD + (size_t)T * TILE;
    sk[tid] = base[tid];
    sk[tid + 1024] = base[tid + 1024];
    __syncthreads();
    int gbase = T * TILE;
    for (int k = 2; k <= TILE; k <<= 1) {
        for (int j = k >> 1; j > 0; j >>= 1) {
            int i = ((tid & ~(j - 1)) << 1) | (tid & (j - 1));
            int ixj = i | j;
            int gi = gbase + i;
            unsigned long long a = sk[i], b = sk[ixj];
            bool doswap = (a < b) ^ ((gi & k) != 0);
            if (doswap) { sk[i] = b; sk[ixj] = a; }
            __syncthreads();
        }
    }
    base[tid] = sk[tid];
    base[tid + 1024] = sk[tid + 1024];
}

__global__ void sort_global_pass(int k, int j) {
    int t = blockIdx.x * 256 + threadIdx.x;
    if (t >= NIMG * NPAD / 2) return;
    int n = t / (NPAD / 2);
    int q = t % (NPAD / 2);
    int i = ((q & ~(j - 1)) << 1) | (q & (j - 1));
    int ixj = i | j;
    unsigned long long* base = g_skey + (size_t)n * NPAD;
    unsigned long long a = base[i], b = base[ixj];
    bool doswap = (a < b) ^ ((i & k) != 0);
    if (doswap) { base[i] = b; base[ixj] = a; }
}

__global__ void __launch_bounds__(1024) sort_local_tail(int k) {
    __shared__ unsigned long long sk[TILE];
    int n = blockIdx.x >> 4;
    int T = blockIdx.x & 15;
    int tid = threadIdx.x;
    unsigned long long* base = g_skey + (size_t)n * NPAD + (size_t)T * TILE;
    sk[tid] = base[tid];
    sk[tid + 1024] = base[tid + 1024];
    __syncthreads();
    int gbase = T * TILE;
    for (int j = 1024; j > 0; j >>= 1) {
        int i = ((tid & ~(j - 1)) << 1) | (tid & (j - 1));
        int ixj = i | j;
        int gi = gbase + i;
        unsigned long long a = sk[i], b = sk[ixj];
        bool doswap = (a < b) ^ ((gi & k) != 0);
        if (doswap) { sk[i] = b; sk[ixj] = a; }
        __syncthreads();
    }
    base[tid] = sk[tid];
    base[tid + 1024] = sk[tid + 1024];
}

__global__ void gather_kernel() {
    int t = blockIdx.x * 256 + threadIdx.x;
    if (t >= NIMG * NPRE) return;
    int n = t / NPRE, l = t % NPRE;
    unsigned long long pk = g_skey[(size_t)n * NPAD + l];
    unsigned int key = (unsigned int)(pk >> 16);
    int idx = NPAD - 1 - (int)(pk & 0xFFFFull);
    g_topkey[t] = key;
    ((float4*)g_topbox)[t] = ((const float4*)g_roi)[n * NANCH + idx];
}

// ---------------- 6: NMS, first-alive scan ----------------
#define NMS_CHUNK 6
__global__ void __launch_bounds__(1024) nms_kernel() {
    __shared__ unsigned int alive[NWORDS];
    __shared__ int s_first;
    int n = blockIdx.x;
    int tid = threadIdx.x;

    float4 myb[NMS_CHUNK];
#pragma unroll
    for (int k = 0; k < NMS_CHUNK; k++) {
        int l = tid + k * 1024;
        myb[k] = (l < NPRE) ? ((const float4*)g_topbox)[n * NPRE + l]
                            : make_float4(0, 0, 0, 0);
    }
    if (tid < NWORDS) {
        unsigned int m = 0;
        for (int b = 0; b < 32; b++) {
            int j = tid * 32 + b;
            if (j < NPRE && g_topkey[n * NPRE + j] > NEGINF_KEY) m |= (1u << b);
        }
        alive[tid] = m;
    }
    __syncthreads();

    int hintw = 0;
    for (int it = 0; it < NPOST; ++it) {
        if (tid == 0) {
            int w = hintw;
            while (w < NWORDS && alive[w] == 0u) w++;
            hintw = w;
            if (w < NWORDS) {
                int f = w * 32 + __ffs(alive[w]) - 1;
                s_first = f;
                g_sel[n * NPOST + it] = f;
                g_val[n * NPOST + it] = 1;
            } else {
                s_first = -1;
                g_sel[n * NPOST + it] = 0;
                g_val[n * NPOST + it] = 0;
            }
        }
        __syncthreads();
        int first = s_first;
        if (first >= 0) {
            float4 bj = ((const float4*)g_topbox)[n * NPRE + first];
            float aj = (bj.z - bj.x) * (bj.w - bj.y);
#pragma unroll
            for (int k = 0; k < NMS_CHUNK; k++) {
                int l = tid + k * 1024;
                if (l < NPRE) {
                    float4 B = myb[k];
                    float ty = fmaxf(bj.x, B.x), tx = fmaxf(bj.y, B.y);
                    float by = fminf(bj.z, B.z), bx = fminf(bj.w, B.w);
                    float ih = fmaxf(by - ty, 0.f);
                    float iw = fmaxf(bx - tx, 0.f);
                    float inter = __fmul_rn(ih, iw);
                    float hl = B.z - B.x;
                    float wl = B.w - B.y;
                    float den = (fmaf(hl, wl, aj) - inter) + 1e-10f;
                    float iou = inter / den;
                    if (iou > 0.7f)
                        atomicAnd(&alive[l >> 5], ~(1u << (l & 31)));
                }
            }
        }
        __syncthreads();
    }
}

// ---------------- 7: emit rois + roi_indices ----------------
__global__ void output_kernel(float* __restrict__ out) {
    int t = blockIdx.x * 256 + threadIdx.x;
    if (t >= NIMG * NPOST) return;
    int n = t / NPOST;
    int sel = g_sel[t];
    int val = g_val[t];
    float4 b = val ? ((const float4*)g_topbox)[n * NPRE + sel] : make_float4(0, 0, 0, 0);
    ((float4*)(out + OFF_ROIS))[t] = b;
    out[OFF_RIDX + t] = (float)n;
}

// ---------------- launch ----------------
extern "C" void kernel_launch(void* const* d_in, const int* in_sizes, int n_in,
                              void* d_out, int out_size)
{
    const float* x   = (const float*)d_in[0];
    const float* c1w = (const float*)d_in[1];
    const float* c1b = (const float*)d_in[2];
    const float* sw  = (const float*)d_in[3];
    const float* sb  = (const float*)d_in[4];
    const float* lw  = (const float*)d_in[5];
    const float* lb  = (const float*)d_in[6];
    const void*  ph  = d_in[7];
    const void*  pw  = d_in[8];
    float* out = (float*)d_out;

    wtrans_kernel<<<(CH * CH * 9 + 255) / 256, 256>>>(c1w);
    conv_chunk_kernel<<<dim3(HH, 8, NIMG * 8), 256>>>(x);
    conv_combine_kernel<<<(NIMG * HW * CH + 255) / 256, 256>>>(c1b);

    heads_kernel<<<NIMG * 388, 256>>>(lw, lb, sw, sb, out);
    fg_kernel<<<(NIMG * NANCH + 255) / 256, 256>>>(out);
    anchor_kernel<<<(NANCH + 255) / 256, 256>>>(out);
    decode_kernel<<<(NIMG * NPAD) / 256, 256>>>(out, ph, pw);

    sort_local_full<<<NIMG * 16, 1024>>>();
    int npairs_blocks = (NIMG * NPAD / 2 + 255) / 256;
    for (int k = 4096; k <= NPAD; k <<= 1) {
        for (int j = k >> 1; j >= TILE; j >>= 1)
            sort_global_pass<<<npairs_blocks, 256>>>(k, j);
        sort_local_tail<<<NIMG * 16, 1024>>>(k);
    }
    gather_kernel<<<(NIMG * NPRE + 255) / 256, 256>>>();

    nms_kernel<<<NIMG, 1024>>>();
    output_kernel<<<(NIMG * NPOST + 255) / 256, 256>>>(out);
}